// round 15
// baseline (speedup 1.0000x reference)
#include <cuda_runtime.h>
#include <math.h>
#include <float.h>

#define NPTS 8192
#define BATCH 2
#define VOXD 64
#define VOXH 128
#define VOXW 128
#define VOX (VOXD*VOXH*VOXW)
#define DPIX (512*512)

// grid: exactly 148 blocks x 512 threads, one per SM.
#define CHAM_BLKS 128   // dirb(4) x ablk(4, 2048 A each) x qc(8, 1024 q each)
#define CL_BLKS   16
#define DP_BLKS   4
#define TOT_BLKS  (CHAM_BLKS + CL_BLKS + DP_BLKS)   // 148
#define TPB 512
#define KA 4            // A points per thread
#define QTILE 512       // q staged in smem per tile (2 tiles per 1024-q chunk)

// partials
__device__ float g_minq[8 * 4 * NPTS];        // [qc][dirb][8192] partial d
__device__ float g_cl[CL_BLKS * 3];           // per cl-block {inter,psum,gsum}
__device__ float g_dp[BATCH * DP_BLKS * 6];   // per dp-block x batch
__device__ unsigned int g_cnt = 0;            // completion counter (self-resetting)

__device__ __forceinline__ float warp_sum(float v) {
#pragma unroll
    for (int o = 16; o > 0; o >>= 1) v += __shfl_xor_sync(0xffffffffu, v, o);
    return v;
}
__device__ __forceinline__ float min3f(float a, float b, float c) {
    return fminf(a, fminf(b, c));
}

// ===========================================================================
// Mega kernel: 148 blocks x 512 threads, static roles, in-kernel finalize.
// ===========================================================================
__global__ void __launch_bounds__(TPB) mega_kernel(const float* __restrict__ pc,
                                                   const float* __restrict__ pv,
                                                   const float* __restrict__ pd,
                                                   const float* __restrict__ gp,
                                                   const float* __restrict__ gv,
                                                   const float* __restrict__ gd,
                                                   const float* __restrict__ dm,
                                                   const int* __restrict__ iter,
                                                   float* __restrict__ out) {
    __shared__ __align__(16) float4 sq[QTILE];   // (qx,qy,qz,|q|^2/2)
    __shared__ float sred[16];
    __shared__ float sqcl[6];
    __shared__ float sqdp[12];
    __shared__ float sct[1];
    __shared__ unsigned int sflag;

    const int bid = blockIdx.x;
    const int tid = threadIdx.x;
    const int lane = tid & 31;
    const int wid = tid >> 5;

    if (bid < CHAM_BLKS) {
        // ---------------- chamfer ----------------
        // d = |p|^2 + 2*min_q(|q|^2/2 - p.q); min over q-chunks done in finalize.
        const int qc = bid & 7;                 // q chunk: 1024 q
        const int ablk = (bid >> 3) & 3;        // A block: 2048 A
        const int db = bid >> 5;                // dir*2 + b
        const int dir = db >> 1;
        const float* A  = (dir == 0 ? pc : gp) + (size_t)(db & 1) * NPTS * 3;
        const float* Bp = (dir == 0 ? gp : pc) + (size_t)(db & 1) * NPTS * 3;

        // 4 A points per thread, strided by TPB for coalescing
        float nax[KA], nay[KA], naz[KA], p2[KA], bm[KA];
#pragma unroll
        for (int k = 0; k < KA; k++) {
            const int a = ablk * 2048 + k * TPB + tid;
            const float ax = A[a * 3 + 0], ay = A[a * 3 + 1], az = A[a * 3 + 2];
            nax[k] = -ax; nay[k] = -ay; naz[k] = -az;
            p2[k] = fmaf(ax, ax, fmaf(ay, ay, az * az));
            bm[k] = FLT_MAX;
        }

        const int qbase = qc * 1024;
#pragma unroll 1
        for (int t0 = 0; t0 < 1024; t0 += QTILE) {
            const int j = qbase + t0 + tid;
            const float qx = Bp[j * 3 + 0];
            const float qy = Bp[j * 3 + 1];
            const float qz = Bp[j * 3 + 2];
            const float s = 0.5f * fmaf(qx, qx, fmaf(qy, qy, qz * qz));
            __syncthreads();
            sq[tid] = make_float4(qx, qy, qz, s);
            __syncthreads();

#pragma unroll 4
            for (int p = 0; p < QTILE; p++) {
                const float4 q = sq[p];   // broadcast
#pragma unroll
                for (int k = 0; k < KA; k++) {
                    float t = fmaf(nax[k], q.x, q.w);
                    t = fmaf(nay[k], q.y, t);
                    t = fmaf(naz[k], q.z, t);
                    bm[k] = fminf(bm[k], t);
                }
            }
        }

        // partial d for this q-chunk (min over chunks commutes with fmaf: monotone)
#pragma unroll
        for (int k = 0; k < KA; k++) {
            const float d = fmaf(2.f, bm[k], p2[k]);
            g_minq[(qc * 4 + db) * NPTS + ablk * 2048 + k * TPB + tid] = d;
        }
    } else if (bid < CHAM_BLKS + CL_BLKS) {
        // ---------------- clDice (16 blocks, one batch per block) ----------------
        // erode(sigmoid(x)) == sigmoid(erode(x)); float4 along W; rolling d.
        const int blk = bid - CHAM_BLKS;
        const int T = blk * TPB + tid;         // 0..8191
        const int b = T >> 12;                 // constant within a block
        const int cg = T & 4095;
        const int h = cg >> 5;
        const int w0 = (cg & 31) * 4;

        const float* P = pv + (size_t)b * VOX;
        const float* G = gv + (size_t)b * VOX;

        const int rm = (h > 0) ? h - 1 : 0;
        const int rp = (h < VOXH - 1) ? h + 1 : h;
        int rowoff[3];
        rowoff[0] = rm * VOXW + w0;
        rowoff[1] = h * VOXW + w0;
        rowoff[2] = rp * VOXW + w0;
        const bool hasL = (w0 > 0);
        const bool hasR = (w0 < VOXW - 4);

        auto inplane = [&](const float* __restrict__ V, int d) -> float4 {
            const int base = d << 14;
            float4 m = make_float4(FLT_MAX, FLT_MAX, FLT_MAX, FLT_MAX);
#pragma unroll
            for (int r = 0; r < 3; r++) {
                const float4 c4 = *(const float4*)(V + base + rowoff[r]);
                const float L = hasL ? __ldg(V + base + rowoff[r] - 1) : c4.x;
                const float R = hasR ? __ldg(V + base + rowoff[r] + 4) : c4.w;
                m.x = fminf(m.x, min3f(L, c4.x, c4.y));
                m.y = fminf(m.y, min3f(c4.x, c4.y, c4.z));
                m.z = fminf(m.z, min3f(c4.y, c4.z, c4.w));
                m.w = fminf(m.w, min3f(c4.z, c4.w, R));
            }
            return m;
        };

        float4 pPrev = inplane(P, 0);
        float4 gPrev = inplane(G, 0);
        float4 pCur = pPrev, gCur = gPrev;

        float si = 0.f, sp = 0.f, sg = 0.f;
#pragma unroll 2
        for (int d = 0; d < VOXD; d++) {
            float4 pNext, gNext;
            if (d < VOXD - 1) {
                pNext = inplane(P, d + 1);
                gNext = inplane(G, d + 1);
            } else {
                pNext = pCur;
                gNext = gCur;
            }
            const float pox = min3f(pPrev.x, pCur.x, pNext.x);
            const float poy = min3f(pPrev.y, pCur.y, pNext.y);
            const float poz = min3f(pPrev.z, pCur.z, pNext.z);
            const float pow_ = min3f(pPrev.w, pCur.w, pNext.w);
            const float gox = min3f(gPrev.x, gCur.x, gNext.x);
            const float goy = min3f(gPrev.y, gCur.y, gNext.y);
            const float goz = min3f(gPrev.z, gCur.z, gNext.z);
            const float gow = min3f(gPrev.w, gCur.w, gNext.w);

            const float sx = __fdividef(1.f, 1.f + __expf(-pox));
            const float sy = __fdividef(1.f, 1.f + __expf(-poy));
            const float sz = __fdividef(1.f, 1.f + __expf(-poz));
            const float sw = __fdividef(1.f, 1.f + __expf(-pow_));

            si = fmaf(sx, gox, fmaf(sy, goy, fmaf(sz, goz, fmaf(sw, gow, si))));
            sp += (sx + sy) + (sz + sw);
            sg += (gox + goy) + (goz + gow);

            pPrev = pCur; gPrev = gCur;
            pCur = pNext; gCur = gNext;
        }

        __shared__ float sr3[3][16];
        const float v0 = warp_sum(si), v1 = warp_sum(sp), v2 = warp_sum(sg);
        if (lane == 0) { sr3[0][wid] = v0; sr3[1][wid] = v1; sr3[2][wid] = v2; }
        __syncthreads();
        if (tid < 3) {
            float a = 0.f;
#pragma unroll
            for (int q = 0; q < 16; q++) a += sr3[tid][q];
            g_cl[blk * 3 + tid] = a;
        }
    } else {
        // ---------------- depth (4 blocks, both batches) ----------------
        const int blkrel = bid - CHAM_BLKS - CL_BLKS;
        const int T = blkrel * TPB + tid;       // 0..2047
        float accd[BATCH][6];
#pragma unroll
        for (int b = 0; b < BATCH; b++) {
            const float* P = pd + (size_t)b * DPIX;
            const float* G = gd + (size_t)b * DPIX;
            const float* M = dm + (size_t)b * DPIX;
            float s0 = 0.f, s1 = 0.f, s2 = 0.f, s3 = 0.f, s4 = 0.f, s5 = 0.f;
#pragma unroll 4
            for (int k = 0; k < 128; k++) {
                const int idx = k * 2048 + T;
                const int hh = idx >> 9;
                const int ww = idx & 511;
                const float p = P[idx];
                const float g = G[idx];
                const float lg = __logf(p + 0.1f) - __logf(g + 0.1f);
                s0 += lg;
                s1 = fmaf(lg, lg, s1);
                if (hh < 511) s2 += fabsf(fabsf(p - P[idx + 512]) - fabsf(g - G[idx + 512]));
                if (ww < 511) s3 += fabsf(fabsf(p - P[idx + 1]) - fabsf(g - G[idx + 1]));
                const float m = M[idx];
                s4 = fmaf(fabsf(p - g), m, s4);
                s5 += m;
            }
            accd[b][0] = s0; accd[b][1] = s1; accd[b][2] = s2;
            accd[b][3] = s3; accd[b][4] = s4; accd[b][5] = s5;
        }

        __shared__ float sr12[12][16];
#pragma unroll
        for (int b = 0; b < BATCH; b++)
#pragma unroll
            for (int q = 0; q < 6; q++) {
                const float v = warp_sum(accd[b][q]);
                if (lane == 0) sr12[b * 6 + q][wid] = v;
            }
        __syncthreads();
        if (tid < 12) {
            float a = 0.f;
#pragma unroll
            for (int q = 0; q < 16; q++) a += sr12[tid][q];
            const int b = tid / 6, c = tid % 6;
            g_dp[(b * DP_BLKS + blkrel) * 6 + c] = a;
        }
    }

    // ================= last-block finalize =================
    __threadfence();
    if (tid == 0) sflag = atomicAdd(&g_cnt, 1u);
    __syncthreads();
    if (sflag != TOT_BLKS - 1) return;
    if (tid == 0) g_cnt = 0;   // reset for next graph replay
    __threadfence();

    // chamfer: min over 8 q-chunks (float4 lanes), then sum
    {
        const float4* mq = (const float4*)g_minq;   // [8][4*NPTS/4]
        const int STR = 4 * NPTS / 4;               // float4s per chunk
        float s = 0.f;
#pragma unroll 2
        for (int i = tid; i < STR; i += TPB) {
            float4 m = mq[i];
#pragma unroll
            for (int c = 1; c < 8; c++) {
                const float4 v = mq[c * STR + i];
                m.x = fminf(m.x, v.x);
                m.y = fminf(m.y, v.y);
                m.z = fminf(m.z, v.z);
                m.w = fminf(m.w, v.w);
            }
            s += (m.x + m.y) + (m.z + m.w);
        }
        s = warp_sum(s);
        if (lane == 0) sred[wid] = s;
    }
    if (tid < 6) {
        const int b = tid / 3, c = tid % 3;
        float a = 0.f;
#pragma unroll
        for (int k = 0; k < 8; k++) a += g_cl[(b * 8 + k) * 3 + c];
        sqcl[tid] = a;
    }
    if (tid >= 32 && tid < 44) {
        const int j = tid - 32;
        const int b = j / 6, c = j % 6;
        float a = 0.f;
#pragma unroll
        for (int k = 0; k < DP_BLKS; k++) a += g_dp[(b * DP_BLKS + k) * 6 + c];
        sqdp[j] = a;
    }
    __syncthreads();
    if (tid == 0) {
        float s = 0.f;
#pragma unroll
        for (int w = 0; w < 16; w++) s += sred[w];
        sct[0] = s;
    }
    __syncthreads();

    if (tid == 0) {
        const float chamfer = sct[0] / (float)(BATCH * NPTS);

        float dice_acc = 0.f;
#pragma unroll
        for (int b = 0; b < BATCH; b++) {
            const float inter = sqcl[b * 3 + 0];
            const float psum = sqcl[b * 3 + 1];
            const float gsum = sqcl[b * 3 + 2];
            dice_acc += (2.f * inter + 1e-5f) / (psum + gsum + 1e-5f);
        }
        const float cldice = 1.f - dice_acc / (float)BATCH;

        float var_acc = 0.f, m2_acc = 0.f;
#pragma unroll
        for (int b = 0; b < BATCH; b++) {
            const float mean = sqdp[b * 6 + 0] / (float)DPIX;
            const float var = sqdp[b * 6 + 1] / (float)DPIX - mean * mean;
            var_acc += var;
            m2_acc += mean * mean;
        }
        const float silog = 10.f * (var_acc / (float)BATCH) + 10.f * (m2_acc / (float)BATCH);

        const float gx = sqdp[0 * 6 + 2] + sqdp[1 * 6 + 2];
        const float gy = sqdp[0 * 6 + 3] + sqdp[1 * 6 + 3];
        const float grad_l1 = gx / (float)(BATCH * 511 * 512) + gy / (float)(BATCH * 512 * 511);

        const float mask_l1 = (sqdp[0 * 6 + 4] + sqdp[1 * 6 + 4]) /
                              (sqdp[0 * 6 + 5] + sqdp[1 * 6 + 5] + 1e-8f);

        const float dloss = silog + grad_l1 + mask_l1;

        int it = iter[0];
        if (it < 1) it = 1;
        const float gamma1 = 2.f * logf((float)it / 20000.f);

        out[0] = gamma1 * chamfer + 0.5f * cldice + 0.01f * dloss;
    }
}

extern "C" void kernel_launch(void* const* d_in, const int* in_sizes, int n_in,
                              void* d_out, int out_size) {
    const float* pc = (const float*)d_in[0];   // pred_centers [2,8192,3]
    const float* pv = (const float*)d_in[1];   // pred_volume  [2,1,64,128,128]
    const float* pd = (const float*)d_in[2];   // pred_depth   [2,512,512]
    const float* gp = (const float*)d_in[3];   // gt_points    [2,8192,3]
    const float* gv = (const float*)d_in[4];   // gt_volume    [2,1,64,128,128]
    const float* gd = (const float*)d_in[5];   // gt_depth     [2,512,512]
    const float* dm = (const float*)d_in[6];   // depth_mask   [2,512,512]
    const int* it   = (const int*)d_in[7];     // iteration (scalar)

    mega_kernel<<<TOT_BLKS, TPB>>>(pc, pv, pd, gp, gv, gd, dm, it, (float*)d_out);
}